// round 2
// baseline (speedup 1.0000x reference)
#include <cuda_runtime.h>
#include <math.h>
#include <stdint.h>

#define NB 4
#define NT 2048
#define NH 16
#define ND 64
#define NE 1024
#define NC 64
#define NCHK 32
#define NBH (NB*NH)

// ---------------- scratch (device globals; no runtime allocation) ----------------
__device__ float g_q  [(size_t)NB*NH*NT*ND];
__device__ float g_k  [(size_t)NB*NH*NT*ND];
__device__ float g_v  [(size_t)NB*NH*NT*ND];
__device__ float g_pp [(size_t)NB*NH*NT*ND];
__device__ float g_ret[(size_t)NB*NH*NT*ND];
__device__ float g_U  [(size_t)NBH*NCHK*ND*ND];
__device__ float g_S  [(size_t)NBH*NCHK*ND*ND];
__device__ float g_W  [(size_t)NBH*NCHK*ND];
__device__ float g_Xn [(size_t)NBH*NCHK*ND];
__device__ float g_stat[(size_t)NBH*NCHK*2];
__device__ float g_norm[NB*2];
__device__ float g_kvp[(size_t)NH*16*ND*ND];

__device__ __forceinline__ unsigned f2tf(float x){
    unsigned r;
    asm("cvt.rna.tf32.f32 %0, %1;" : "=r"(r) : "f"(x));
    return r;
}

// ================= K1: projection GEMM (TF32 mma, 128x128 tiles) =================
__global__ void __launch_bounds__(256) k_proj(const float* __restrict__ X,
                                              const float* __restrict__ W,
                                              int sel)
{
    float* dst = (sel==0) ? g_q : (sel==1) ? g_k : g_v;
    __shared__ float As[128*20];
    __shared__ float Bs[16*136];

    const int tid = threadIdx.x;
    const int rowBase = blockIdx.y*128, colBase = blockIdx.x*128;
    const int warp = tid>>5, lane = tid&31;
    const int wm = warp&3, wn = warp>>2;
    const int g = lane>>2, t4 = lane&3;

    float acc[2][8][4];
#pragma unroll
    for (int a=0;a<2;a++)
#pragma unroll
      for (int b=0;b<8;b++)
#pragma unroll
        for (int c=0;c<4;c++) acc[a][b][c]=0.f;

    for (int kb=0; kb<NE; kb+=16){
#pragma unroll
        for (int l=0;l<8;l++){
            int e = tid + l*256;
            As[(e>>4)*20 + (e&15)] = X[(size_t)(rowBase+(e>>4))*NE + kb + (e&15)];
        }
#pragma unroll
        for (int l=0;l<8;l++){
            int e = tid + l*256;
            Bs[(e>>7)*136 + (e&127)] = W[(size_t)(kb+(e>>7))*NE + colBase + (e&127)];
        }
        __syncthreads();
#pragma unroll
        for (int k0=0;k0<16;k0+=8){
            unsigned af[2][4];
#pragma unroll
            for (int mt=0;mt<2;mt++){
                int r0 = wm*32 + mt*16;
                af[mt][0] = f2tf(As[(r0+g  )*20 + k0 + t4    ]);
                af[mt][1] = f2tf(As[(r0+g+8)*20 + k0 + t4    ]);
                af[mt][2] = f2tf(As[(r0+g  )*20 + k0 + t4 + 4]);
                af[mt][3] = f2tf(As[(r0+g+8)*20 + k0 + t4 + 4]);
            }
#pragma unroll
            for (int nt=0;nt<8;nt++){
                int c0 = wn*64 + nt*8;
                unsigned b0 = f2tf(Bs[(k0+t4  )*136 + c0 + g]);
                unsigned b1 = f2tf(Bs[(k0+t4+4)*136 + c0 + g]);
#pragma unroll
                for (int mt=0;mt<2;mt++){
                    asm volatile(
                      "mma.sync.aligned.m16n8k8.row.col.f32.tf32.tf32.f32 "
                      "{%0,%1,%2,%3},{%4,%5,%6,%7},{%8,%9},{%0,%1,%2,%3};"
                      : "+f"(acc[mt][nt][0]), "+f"(acc[mt][nt][1]),
                        "+f"(acc[mt][nt][2]), "+f"(acc[mt][nt][3])
                      : "r"(af[mt][0]), "r"(af[mt][1]), "r"(af[mt][2]), "r"(af[mt][3]),
                        "r"(b0), "r"(b1));
                }
            }
        }
        __syncthreads();
    }
#pragma unroll
    for (int mt=0;mt<2;mt++)
#pragma unroll
    for (int nt=0;nt<8;nt++)
#pragma unroll
    for (int idx=0;idx<4;idx++){
        int row = rowBase + wm*32 + mt*16 + g + ((idx>>1)?8:0);
        int col = colBase + wn*64 + nt*8 + t4*2 + (idx&1);
        int b_ = row>>11, t_ = row&2047, h_ = col>>6, d_ = col&63;
        dst[(((size_t)(b_*NH+h_))*NT + t_)*ND + d_] = acc[mt][nt][idx];
    }
}

// ================= K2: per-chunk U_j, pp, W_j =================
__global__ void __launch_bounds__(256) k_pass1(const float* __restrict__ pkv)
{
    __shared__ float bufA[64*68];
    __shared__ float bufB[64*68];
    __shared__ float Wred[16*64];
    __shared__ float gp[65];
    int tid=threadIdx.x, bid=blockIdx.x;
    int j=bid&31, bh=bid>>5, h=bh&15;
    size_t base = ((size_t)bh*NT + (size_t)j*NC)*ND;
    if (tid<=64){
        double gd = 1.0 - exp2(-5.0-(double)h);
        gp[tid]=(float)pow(gd,(double)tid);
    }
#pragma unroll
    for (int l=0;l<4;l++){
        int idx = tid + l*256;
        *(float4*)(bufA + (idx>>4)*68 + (idx&15)*4) = *(const float4*)(g_k + base + (size_t)idx*4);
        *(float4*)(bufB + (idx>>4)*68 + (idx&15)*4) = *(const float4*)(g_v + base + (size_t)idx*4);
    }
    __syncthreads();
    int hg=tid>>4, lg=tid&15;
    int d0=4*hg, e0=4*lg;
    float accU[4][4]={};
    for (int i=0;i<64;i++){
        float w = gp[63-i];
        float4 kk = *(float4*)(bufA + i*68 + d0);
        float4 vv = *(float4*)(bufB + i*68 + e0);
        float kr[4]={kk.x*w,kk.y*w,kk.z*w,kk.w*w};
        float vr[4]={vv.x,vv.y,vv.z,vv.w};
#pragma unroll
        for (int dd=0;dd<4;dd++)
#pragma unroll
        for (int ee=0;ee<4;ee++) accU[dd][ee] += kr[dd]*vr[ee];
    }
    float* Up = g_U + (size_t)bid*4096;
#pragma unroll
    for (int dd=0;dd<4;dd++)
        *(float4*)(Up + (d0+dd)*64 + e0) = make_float4(accU[dd][0],accU[dd][1],accU[dd][2],accU[dd][3]);
    __syncthreads();
    // QT into bufA, A(past_kv) into bufB
#pragma unroll
    for (int l=0;l<4;l++){
        int idx=tid+l*256;
        int i=idx>>4, d4=(idx&15)*4;
        float4 q4 = *(const float4*)(g_q + base + (size_t)idx*4);
        bufA[(d4  )*68 + i]=q4.x;
        bufA[(d4+1)*68 + i]=q4.y;
        bufA[(d4+2)*68 + i]=q4.z;
        bufA[(d4+3)*68 + i]=q4.w;
        *(float4*)(bufB + i*68 + d4) = *(const float4*)(pkv + (size_t)h*4096 + (size_t)idx*4);
    }
    __syncthreads();
    int i0 = 4*hg;
    float accP[4][4]={};
    for (int d=0;d<64;d++){
        float4 qq = *(float4*)(bufA + d*68 + i0);
        float4 aa = *(float4*)(bufB + d*68 + e0);
        float qr[4]={qq.x,qq.y,qq.z,qq.w}, ar[4]={aa.x,aa.y,aa.z,aa.w};
#pragma unroll
        for (int ii=0;ii<4;ii++)
#pragma unroll
        for (int ee=0;ee<4;ee++) accP[ii][ee]+=qr[ii]*ar[ee];
    }
    float* ppp = g_pp + base;
#pragma unroll
    for (int ii=0;ii<4;ii++)
        *(float4*)(ppp + (size_t)(i0+ii)*64 + e0) = make_float4(accP[ii][0],accP[ii][1],accP[ii][2],accP[ii][3]);
    // W_j[e] = sum_i gamma^i pp[i,e]
    float wp[4]={0,0,0,0};
#pragma unroll
    for (int ii=0;ii<4;ii++){
        float g_i = gp[i0+ii];
#pragma unroll
        for (int ee=0;ee<4;ee++) wp[ee] += g_i*accP[ii][ee];
    }
#pragma unroll
    for (int ee=0;ee<4;ee++) Wred[hg*64 + e0+ee] = wp[ee];
    __syncthreads();
    if (tid<64){
        float s=0;
#pragma unroll
        for (int r=0;r<16;r++) s += Wred[r*64 + tid];
        g_W[(size_t)bid*64 + tid] = s;
    }
}

// ================= K3: chunk scans (forward state, backward suffix carry) =========
__global__ void __launch_bounds__(256) k_scan()
{
    int bh = blockIdx.x, tid = threadIdx.x;
    int h = bh&15;
    double gd = 1.0 - exp2(-5.0-(double)h);
    float g64 = (float)pow(gd,64.0);
    float S[16];
#pragma unroll
    for (int r=0;r<16;r++) S[r]=0.f;
    for (int j=0;j<NCHK;j++){
        size_t o = ((size_t)bh*NCHK+j)*4096;
#pragma unroll
        for (int r=0;r<16;r++){
            int idx = tid + r*256;
            g_S[o+idx] = S[r];
            S[r] = g64*S[r] + g_U[o+idx];
        }
    }
    if (tid<64){
        float X=0.f;
        for (int j=NCHK-1;j>=0;--j){
            size_t o2 = ((size_t)bh*NCHK+j)*64;
            g_Xn[o2+tid] = X;
            X = g64*X + g_W[o2+tid];
        }
    }
}

// ================= K4: per-chunk finalize (inner + state + cross) =================
__global__ void __launch_bounds__(256) k_pass3()
{
    __shared__ float b1[64*68];
    __shared__ float b2[64*68];
    __shared__ float gp[65];
    __shared__ float Xs[64];
    __shared__ float redS[8], redQ[8];
    int tid=threadIdx.x, bid=blockIdx.x;
    int j=bid&31, bh=bid>>5, h=bh&15;
    size_t base=((size_t)bh*NT+(size_t)j*NC)*ND;
    if (tid<=64){
        double gd = 1.0 - exp2(-5.0-(double)h);
        gp[tid]=(float)pow(gd,(double)tid);
    }
    if (tid<64) Xs[tid] = g_Xn[((size_t)bh*NCHK+j)*64 + tid];
    // QT -> b1, KT -> b2
#pragma unroll
    for (int l=0;l<4;l++){
        int idx=tid+l*256;
        int i=idx>>4, d4=(idx&15)*4;
        float4 q4 = *(const float4*)(g_q + base + (size_t)idx*4);
        b1[(d4  )*68+i]=q4.x; b1[(d4+1)*68+i]=q4.y;
        b1[(d4+2)*68+i]=q4.z; b1[(d4+3)*68+i]=q4.w;
        float4 k4 = *(const float4*)(g_k + base + (size_t)idx*4);
        b2[(d4  )*68+i]=k4.x; b2[(d4+1)*68+i]=k4.y;
        b2[(d4+2)*68+i]=k4.z; b2[(d4+3)*68+i]=k4.w;
    }
    __syncthreads();
    int ig=tid>>4, lg=tid&15;
    int i0=4*ig, s0=4*lg, e0=4*lg;
    float P[4][4]={};
    for (int d=0;d<64;d++){
        float4 qq=*(float4*)(b1+d*68+i0);
        float4 kk=*(float4*)(b2+d*68+s0);
        float qr[4]={qq.x,qq.y,qq.z,qq.w}, kr[4]={kk.x,kk.y,kk.z,kk.w};
#pragma unroll
        for (int ii=0;ii<4;ii++)
#pragma unroll
        for (int ss=0;ss<4;ss++) P[ii][ss]+=qr[ii]*kr[ss];
    }
#pragma unroll
    for (int ii=0;ii<4;ii++)
#pragma unroll
    for (int ss=0;ss<4;ss++){
        int di = (i0+ii)-(s0+ss);
        P[ii][ss] = (di>=0) ? P[ii][ss]*gp[di] : 0.f;
    }
    // S chunk -> b2 (QT still in b1)
    __syncthreads();
#pragma unroll
    for (int l=0;l<4;l++){
        int idx=tid+l*256;
        *(float4*)(b2 + (idx>>4)*68 + (idx&15)*4) =
            *(const float4*)(g_S + ((size_t)bh*NCHK+j)*4096 + (size_t)idx*4);
    }
    __syncthreads();
    float QS[4][4]={};
    for (int d=0;d<64;d++){
        float4 qq=*(float4*)(b1+d*68+i0);
        float4 s4=*(float4*)(b2+d*68+e0);
        float qr[4]={qq.x,qq.y,qq.z,qq.w}, sr[4]={s4.x,s4.y,s4.z,s4.w};
#pragma unroll
        for (int ii=0;ii<4;ii++)
#pragma unroll
        for (int ee=0;ee<4;ee++) QS[ii][ee]+=qr[ii]*sr[ee];
    }
    // PT -> b1, V -> b2
    __syncthreads();
#pragma unroll
    for (int ii=0;ii<4;ii++)
#pragma unroll
    for (int ss=0;ss<4;ss++) b1[(s0+ss)*68 + (i0+ii)] = P[ii][ss];
#pragma unroll
    for (int l=0;l<4;l++){
        int idx=tid+l*256;
        *(float4*)(b2 + (idx>>4)*68 + (idx&15)*4) =
            *(const float4*)(g_v + base + (size_t)idx*4);
    }
    __syncthreads();
    float R[4][4];
#pragma unroll
    for (int ii=0;ii<4;ii++){
        float gi = gp[i0+ii+1];
#pragma unroll
        for (int ee=0;ee<4;ee++) R[ii][ee] = gi*QS[ii][ee];
    }
    for (int s=0;s<64;s++){
        float4 pt=*(float4*)(b1+s*68+i0);
        float4 vv=*(float4*)(b2+s*68+e0);
        float pr[4]={pt.x,pt.y,pt.z,pt.w}, vr[4]={vv.x,vv.y,vv.z,vv.w};
#pragma unroll
        for (int ii=0;ii<4;ii++)
#pragma unroll
        for (int ee=0;ee<4;ee++) R[ii][ee]+=pr[ii]*vr[ee];
    }
    // pp chunk -> b1, in-chunk suffix scan
    __syncthreads();
#pragma unroll
    for (int l=0;l<4;l++){
        int idx=tid+l*256;
        *(float4*)(b1 + (idx>>4)*68 + (idx&15)*4) =
            *(const float4*)(g_pp + base + (size_t)idx*4);
    }
    __syncthreads();
    if (tid<64){
        float c=0.f, ga=gp[1];
        for (int i=63;i>=0;--i){
            c = b1[i*68+tid] + ga*c;
            b1[i*68+tid] = c;
        }
    }
    __syncthreads();
    float s1=0.f, s2=0.f;
#pragma unroll
    for (int ii=0;ii<4;ii++){
        float gx = gp[64-(i0+ii)];
#pragma unroll
        for (int ee=0;ee<4;ee++){
            float val = R[ii][ee] + b1[(i0+ii)*68 + (e0+ee)] + gx*Xs[e0+ee];
            R[ii][ee]=val;
            s1 += val; s2 += val*val;
        }
        *(float4*)(g_ret + base + (size_t)(i0+ii)*64 + e0) =
            make_float4(R[ii][0],R[ii][1],R[ii][2],R[ii][3]);
    }
    // block stats
#pragma unroll
    for (int o=16;o>0;o>>=1){
        s1 += __shfl_down_sync(0xffffffffu, s1, o);
        s2 += __shfl_down_sync(0xffffffffu, s2, o);
    }
    if ((tid&31)==0){ redS[tid>>5]=s1; redQ[tid>>5]=s2; }
    __syncthreads();
    if (tid==0){
        float a=0.f,bq=0.f;
#pragma unroll
        for (int w=0;w<8;w++){ a+=redS[w]; bq+=redQ[w]; }
        g_stat[(size_t)bid*2  ]=a;
        g_stat[(size_t)bid*2+1]=bq;
    }
}

// ================= K5: per-batch GroupNorm stats =================
__global__ void __launch_bounds__(512) k_stats()
{
    __shared__ float r1[512], r2[512];
    int b=blockIdx.x, tid=threadIdx.x;
    r1[tid]=g_stat[(size_t)(b*512+tid)*2];
    r2[tid]=g_stat[(size_t)(b*512+tid)*2+1];
    __syncthreads();
    for (int o=256;o>0;o>>=1){
        if (tid<o){ r1[tid]+=r1[tid+o]; r2[tid]+=r2[tid+o]; }
        __syncthreads();
    }
    if (tid==0){
        const float N = (float)((size_t)NH*NT*ND);
        float mu = r1[0]/N;
        float var = r2[0]/N - mu*mu;
        g_norm[b*2]=mu;
        g_norm[b*2+1]=rsqrtf(var+1e-5f);
    }
}

// ================= K6: normalize + layout to [B,T,NE] =================
__global__ void __launch_bounds__(256) k_out(const float* __restrict__ gnw,
                                             const float* __restrict__ gnb,
                                             float* __restrict__ out)
{
    int bid=blockIdx.x;
    int b=bid>>11, t=bid&2047;
    int tid=threadIdx.x;
    int h=tid>>4, d4=(tid&15)*4;
    float mu=g_norm[b*2], rs=g_norm[b*2+1];
    float w = gnw[h]*rs;
    float bb = gnb[h] - mu*w;
    float4 xv = *(const float4*)(g_ret + (((size_t)(b*NH+h))*NT + t)*ND + d4);
    float4 yv = make_float4(xv.x*w+bb, xv.y*w+bb, xv.z*w+bb, xv.w*w+bb);
    *(float4*)(out + (size_t)bid*NE + h*ND + d4) = yv;
}

// ================= K7: kv partials =================
__global__ void __launch_bounds__(256) k_kvpart()
{
    __shared__ float bk[64*68];
    __shared__ float bv[64*68];
    int bid=blockIdx.x;
    int h=bid>>4, b=(bid>>2)&3, part=bid&3;
    int tid=threadIdx.x;
    int hg=tid>>4, lg=tid&15;
    int d0=4*hg, e0=4*lg;
    size_t base = (((size_t)(b*NH+h))*NT + (size_t)part*512)*ND;
    float acc[4][4]={};
    for (int c=0;c<8;c++){
        __syncthreads();
#pragma unroll
        for (int l=0;l<4;l++){
            int idx=tid+l*256;
            *(float4*)(bk + (idx>>4)*68 + (idx&15)*4) =
                *(const float4*)(g_k + base + (size_t)c*4096 + (size_t)idx*4);
            *(float4*)(bv + (idx>>4)*68 + (idx&15)*4) =
                *(const float4*)(g_v + base + (size_t)c*4096 + (size_t)idx*4);
        }
        __syncthreads();
        for (int i=0;i<64;i++){
            float4 kk=*(float4*)(bk+i*68+d0);
            float4 vv=*(float4*)(bv+i*68+e0);
            float kr[4]={kk.x,kk.y,kk.z,kk.w}, vr[4]={vv.x,vv.y,vv.z,vv.w};
#pragma unroll
            for (int dd=0;dd<4;dd++)
#pragma unroll
            for (int ee=0;ee<4;ee++) acc[dd][ee]+=kr[dd]*vr[ee];
        }
    }
    float* outp = g_kvp + ((size_t)(h*16 + b*4 + part))*4096;
#pragma unroll
    for (int dd=0;dd<4;dd++)
        *(float4*)(outp + (d0+dd)*64 + e0) = make_float4(acc[dd][0],acc[dd][1],acc[dd][2],acc[dd][3]);
}

// ================= K8: kv reduce + decay =================
__global__ void __launch_bounds__(256) k_kvout(const float* __restrict__ pkv,
                                               float* __restrict__ out_kv)
{
    int h=blockIdx.x, tid=threadIdx.x;
    double gd = 1.0 - exp2(-5.0-(double)h);
    float g1=(float)gd;
#pragma unroll
    for (int r=0;r<16;r++){
        int idx = tid + r*256;
        float s=0.f;
#pragma unroll
        for (int p=0;p<16;p++) s += g_kvp[((size_t)(h*16+p))*4096 + idx];
        out_kv[(size_t)h*4096 + idx] = g1*pkv[(size_t)h*4096 + idx] + 0.25f*s;
    }
}

extern "C" void kernel_launch(void* const* d_in, const int* in_sizes, int n_in,
                              void* d_out, int out_size)
{
    const float* x   = (const float*)d_in[0];
    const float* pkv = (const float*)d_in[1];
    const float* Wq  = (const float*)d_in[2];
    const float* Wk  = (const float*)d_in[3];
    const float* Wv  = (const float*)d_in[4];
    const float* gnw = (const float*)d_in[5];
    const float* gnb = (const float*)d_in[6];
    float* out = (float*)d_out;

    dim3 gproj(8, 64);
    k_proj<<<gproj, 256>>>(x, Wq, 0);
    k_proj<<<gproj, 256>>>(x, Wk, 1);
    k_proj<<<gproj, 256>>>(x, Wv, 2);
    k_pass1<<<NBH*NCHK, 256>>>(pkv);
    k_scan<<<NBH, 256>>>();
    k_pass3<<<NBH*NCHK, 256>>>();
    k_stats<<<NB, 512>>>();
    k_out<<<NB*NT, 256>>>(gnw, gnb, out);
    k_kvpart<<<256, 256>>>();
    k_kvout<<<NH, 256>>>(pkv, out + (size_t)NB*NT*NE);
}

// round 3
// speedup vs baseline: 1.5170x; 1.5170x over previous
#include <cuda_runtime.h>
#include <math.h>
#include <stdint.h>

#define NB 4
#define NT 2048
#define NH 16
#define ND 64
#define NE 1024
#define NC 64
#define NCHK 32
#define NBH (NB*NH)

// ---------------- scratch (device globals; no runtime allocation) ----------------
__device__ float g_q  [(size_t)NB*NH*NT*ND];
__device__ float g_k  [(size_t)NB*NH*NT*ND];
__device__ float g_v  [(size_t)NB*NH*NT*ND];
__device__ float g_ret[(size_t)NB*NH*NT*ND];
__device__ float g_U  [(size_t)NBH*NCHK*ND*ND];
__device__ float g_S  [(size_t)NBH*NCHK*ND*ND];
__device__ float g_kvc[(size_t)NBH*NCHK*ND*ND];
__device__ float g_W  [(size_t)NBH*NCHK*ND];
__device__ float g_Xn [(size_t)NBH*NCHK*ND];
__device__ float g_stat[(size_t)NBH*NCHK*2];
__device__ float g_norm[NB*2];

__device__ __forceinline__ unsigned f2tf(float x){
    unsigned r;
    asm("cvt.rna.tf32.f32 %0, %1;" : "=r"(r) : "f"(x));
    return r;
}

#define CP16(dst_u32, src) \
    asm volatile("cp.async.ca.shared.global [%0], [%1], 16;" :: "r"(dst_u32), "l"(src))

// ================= K1: fused QKV projection (TF32 mma, cp.async double-buffered) ===
__global__ void __launch_bounds__(256) k_proj3(const float* __restrict__ X,
                                               const float* __restrict__ Wq,
                                               const float* __restrict__ Wk,
                                               const float* __restrict__ Wv)
{
    const int sel = blockIdx.z;
    const float* W = (sel==0)?Wq:(sel==1)?Wk:Wv;
    float* dst = (sel==0)?g_q:(sel==1)?g_k:g_v;

    __shared__ float As[2][128*20];
    __shared__ float Bs[2][16*136];

    const int tid = threadIdx.x;
    const int rowBase = blockIdx.y*128, colBase = blockIdx.x*128;
    const int warp = tid>>5, lane = tid&31;
    const int wm = warp&3, wn = warp>>2;
    const int g = lane>>2, t4 = lane&3;

    const int ar0 = tid>>2, ac0 = (tid&3)*4;     // A tile: rows 0..63 (+64), k-col 4-group
    const int br0 = tid>>5, bc0 = (tid&31)*4;    // B tile: rows 0..7 (+8), col 4-group

    const unsigned sA = (unsigned)__cvta_generic_to_shared(&As[0][0]);
    const unsigned sB = (unsigned)__cvta_generic_to_shared(&Bs[0][0]);
    const unsigned stA = 2560u*4u, stB = 2176u*4u;

    float acc[2][8][4];
#pragma unroll
    for (int a=0;a<2;a++)
#pragma unroll
      for (int b=0;b<8;b++)
#pragma unroll
        for (int c=0;c<4;c++) acc[a][b][c]=0.f;

    auto issue = [&](int kb, int st){
        const float* xs = X + (size_t)rowBase*NE + kb;
        CP16(sA + st*stA + (unsigned)((ar0    )*20 + ac0)*4u, xs + (size_t)(ar0    )*NE + ac0);
        CP16(sA + st*stA + (unsigned)((ar0+64 )*20 + ac0)*4u, xs + (size_t)(ar0+64 )*NE + ac0);
        const float* ws = W + (size_t)kb*NE + colBase;
        CP16(sB + st*stB + (unsigned)((br0   )*136 + bc0)*4u, ws + (size_t)(br0   )*NE + bc0);
        CP16(sB + st*stB + (unsigned)((br0+8 )*136 + bc0)*4u, ws + (size_t)(br0+8 )*NE + bc0);
        asm volatile("cp.async.commit_group;" ::: "memory");
    };

    issue(0, 0);
    const int NIT = NE/16;
    for (int it=0; it<NIT; it++){
        const int st = it&1;
        if (it+1<NIT){
            issue((it+1)*16, st^1);
            asm volatile("cp.async.wait_group 1;" ::: "memory");
        } else {
            asm volatile("cp.async.wait_group 0;" ::: "memory");
        }
        __syncthreads();
        const float* Ap = As[st];
        const float* Bp = Bs[st];
#pragma unroll
        for (int k0=0;k0<16;k0+=8){
            unsigned af[2][4];
#pragma unroll
            for (int mt=0;mt<2;mt++){
                int r0 = wm*32 + mt*16;
                af[mt][0] = f2tf(Ap[(r0+g  )*20 + k0 + t4    ]);
                af[mt][1] = f2tf(Ap[(r0+g+8)*20 + k0 + t4    ]);
                af[mt][2] = f2tf(Ap[(r0+g  )*20 + k0 + t4 + 4]);
                af[mt][3] = f2tf(Ap[(r0+g+8)*20 + k0 + t4 + 4]);
            }
#pragma unroll
            for (int nt=0;nt<8;nt++){
                int c0 = wn*64 + nt*8;
                unsigned b0 = f2tf(Bp[(k0+t4  )*136 + c0 + g]);
                unsigned b1 = f2tf(Bp[(k0+t4+4)*136 + c0 + g]);
#pragma unroll
                for (int mt=0;mt<2;mt++){
                    asm volatile(
                      "mma.sync.aligned.m16n8k8.row.col.f32.tf32.tf32.f32 "
                      "{%0,%1,%2,%3},{%4,%5,%6,%7},{%8,%9},{%0,%1,%2,%3};"
                      : "+f"(acc[mt][nt][0]), "+f"(acc[mt][nt][1]),
                        "+f"(acc[mt][nt][2]), "+f"(acc[mt][nt][3])
                      : "r"(af[mt][0]), "r"(af[mt][1]), "r"(af[mt][2]), "r"(af[mt][3]),
                        "r"(b0), "r"(b1));
                }
            }
        }
        __syncthreads();
    }
#pragma unroll
    for (int mt=0;mt<2;mt++)
#pragma unroll
    for (int nt=0;nt<8;nt++)
#pragma unroll
    for (int idx=0;idx<4;idx++){
        int row = rowBase + wm*32 + mt*16 + g + ((idx>>1)?8:0);
        int col = colBase + wn*64 + nt*8 + t4*2 + (idx&1);
        int b_ = row>>11, t_ = row&2047, h_ = col>>6, d_ = col&63;
        dst[(((size_t)(b_*NH+h_))*NT + t_)*ND + d_] = acc[mt][nt][idx];
    }
}

// ================= K2: per-chunk U_j (decayed K^T V), plain KV, W_j =================
__global__ void __launch_bounds__(256) k_pass1(const float* __restrict__ pkv)
{
    __shared__ float bufA[64*68];
    __shared__ float bufB[64*68];
    __shared__ float red[4*64];
    __shared__ float qw[64];
    __shared__ float gp[65];
    int tid=threadIdx.x, bid=blockIdx.x;
    int j=bid&31, bh=bid>>5, h=bh&15;
    size_t base = ((size_t)bh*NT + (size_t)j*NC)*ND;
    if (tid<=64){
        double gd = 1.0 - exp2(-5.0-(double)h);
        gp[tid]=(float)pow(gd,(double)tid);
    }
#pragma unroll
    for (int l=0;l<4;l++){
        int idx = tid + l*256;
        *(float4*)(bufA + (idx>>4)*68 + (idx&15)*4) = *(const float4*)(g_k + base + (size_t)idx*4);
        *(float4*)(bufB + (idx>>4)*68 + (idx&15)*4) = *(const float4*)(g_v + base + (size_t)idx*4);
    }
    __syncthreads();
    int hg=tid>>4, lg=tid&15;
    int d0=4*hg, e0=4*lg;
    float accU[4][4]={}, accKV[4][4]={};
    for (int i=0;i<64;i++){
        float w = gp[63-i];
        float4 kk = *(float4*)(bufA + i*68 + d0);
        float4 vv = *(float4*)(bufB + i*68 + e0);
        float kr[4]={kk.x,kk.y,kk.z,kk.w};
        float wk[4]={kk.x*w,kk.y*w,kk.z*w,kk.w*w};
        float vr[4]={vv.x,vv.y,vv.z,vv.w};
#pragma unroll
        for (int dd=0;dd<4;dd++)
#pragma unroll
        for (int ee=0;ee<4;ee++){
            accKV[dd][ee] += kr[dd]*vr[ee];
            accU [dd][ee] += wk[dd]*vr[ee];
        }
    }
    float* Up = g_U  + (size_t)bid*4096;
    float* Kp = g_kvc+ (size_t)bid*4096;
#pragma unroll
    for (int dd=0;dd<4;dd++){
        *(float4*)(Up + (d0+dd)*64 + e0) = make_float4(accU [dd][0],accU [dd][1],accU [dd][2],accU [dd][3]);
        *(float4*)(Kp + (d0+dd)*64 + e0) = make_float4(accKV[dd][0],accKV[dd][1],accKV[dd][2],accKV[dd][3]);
    }
    __syncthreads();
    // q chunk -> bufA [i][d]
#pragma unroll
    for (int l=0;l<4;l++){
        int idx = tid + l*256;
        *(float4*)(bufA + (idx>>4)*68 + (idx&15)*4) = *(const float4*)(g_q + base + (size_t)idx*4);
    }
    __syncthreads();
    // qw[d] = sum_i gamma^i q[i,d]
    int r = tid>>6, d = tid&63;
    float s = 0.f;
#pragma unroll
    for (int i=r*16;i<r*16+16;i++) s += gp[i]*bufA[i*68 + d];
    red[r*64 + d] = s;
    __syncthreads();
    if (tid<64) qw[tid] = red[tid] + red[64+tid] + red[128+tid] + red[192+tid];
    __syncthreads();
    // W_j[e] = sum_d qw[d] * A[d,e]
    const float* A = pkv + (size_t)h*4096;
    float s2 = 0.f;
#pragma unroll
    for (int dd=r*16; dd<r*16+16; dd++) s2 += qw[dd]*A[dd*64 + d];
    red[r*64 + d] = s2;
    __syncthreads();
    if (tid<64) g_W[(size_t)bid*64 + tid] = red[tid] + red[64+tid] + red[128+tid] + red[192+tid];
}

// ================= K3: chunk scans (forward state, backward suffix carry) =========
__global__ void __launch_bounds__(256) k_scan()
{
    int bh = blockIdx.x, tid = threadIdx.x;
    int h = bh&15;
    double gd = 1.0 - exp2(-5.0-(double)h);
    float g64 = (float)pow(gd,64.0);
    float S[16];
#pragma unroll
    for (int r=0;r<16;r++) S[r]=0.f;
    for (int j=0;j<NCHK;j++){
        size_t o = ((size_t)bh*NCHK+j)*4096;
#pragma unroll
        for (int r=0;r<16;r++){
            int idx = tid + r*256;
            g_S[o+idx] = S[r];
            S[r] = g64*S[r] + g_U[o+idx];
        }
    }
    if (tid<64){
        float X=0.f;
        for (int j=NCHK-1;j>=0;--j){
            size_t o2 = ((size_t)bh*NCHK+j)*64;
            g_Xn[o2+tid] = X;
            X = g64*X + g_W[o2+tid];
        }
    }
}

// ================= K4: per-chunk finalize (inner + state + cross) =================
__global__ void __launch_bounds__(256) k_pass3(const float* __restrict__ pkv)
{
    __shared__ float b1[64*68];
    __shared__ float b2[64*68];
    __shared__ float gp[65];
    __shared__ float Xs[64];
    __shared__ float redS[8], redQ[8];
    int tid=threadIdx.x, bid=blockIdx.x;
    int j=bid&31, bh=bid>>5, h=bh&15;
    size_t base=((size_t)bh*NT+(size_t)j*NC)*ND;
    if (tid<=64){
        double gd = 1.0 - exp2(-5.0-(double)h);
        gp[tid]=(float)pow(gd,(double)tid);
    }
    if (tid<64) Xs[tid] = g_Xn[((size_t)bh*NCHK+j)*64 + tid];
    // QT -> b1, KT -> b2
#pragma unroll
    for (int l=0;l<4;l++){
        int idx=tid+l*256;
        int i=idx>>4, d4=(idx&15)*4;
        float4 q4 = *(const float4*)(g_q + base + (size_t)idx*4);
        b1[(d4  )*68+i]=q4.x; b1[(d4+1)*68+i]=q4.y;
        b1[(d4+2)*68+i]=q4.z; b1[(d4+3)*68+i]=q4.w;
        float4 k4 = *(const float4*)(g_k + base + (size_t)idx*4);
        b2[(d4  )*68+i]=k4.x; b2[(d4+1)*68+i]=k4.y;
        b2[(d4+2)*68+i]=k4.z; b2[(d4+3)*68+i]=k4.w;
    }
    __syncthreads();
    int ig=tid>>4, lg=tid&15;
    int i0=4*ig, s0=4*lg, e0=4*lg;
    // P = (Q K^T) .* D
    float P[4][4]={};
    for (int d=0;d<64;d++){
        float4 qq=*(float4*)(b1+d*68+i0);
        float4 kk=*(float4*)(b2+d*68+s0);
        float qr[4]={qq.x,qq.y,qq.z,qq.w}, kr[4]={kk.x,kk.y,kk.z,kk.w};
#pragma unroll
        for (int ii=0;ii<4;ii++)
#pragma unroll
        for (int ss=0;ss<4;ss++) P[ii][ss]+=qr[ii]*kr[ss];
    }
#pragma unroll
    for (int ii=0;ii<4;ii++)
#pragma unroll
    for (int ss=0;ss<4;ss++){
        int di = (i0+ii)-(s0+ss);
        P[ii][ss] = (di>=0) ? P[ii][ss]*gp[di] : 0.f;
    }
    // S chunk -> b2 ; QS = Q @ S
    __syncthreads();
#pragma unroll
    for (int l=0;l<4;l++){
        int idx=tid+l*256;
        *(float4*)(b2 + (idx>>4)*68 + (idx&15)*4) =
            *(const float4*)(g_S + ((size_t)bh*NCHK+j)*4096 + (size_t)idx*4);
    }
    __syncthreads();
    float QS[4][4]={};
    for (int d=0;d<64;d++){
        float4 qq=*(float4*)(b1+d*68+i0);
        float4 s4=*(float4*)(b2+d*68+e0);
        float qr[4]={qq.x,qq.y,qq.z,qq.w}, sr[4]={s4.x,s4.y,s4.z,s4.w};
#pragma unroll
        for (int ii=0;ii<4;ii++)
#pragma unroll
        for (int ee=0;ee<4;ee++) QS[ii][ee]+=qr[ii]*sr[ee];
    }
    // A -> b2 ; PP = Q @ A (regs)
    __syncthreads();
#pragma unroll
    for (int l=0;l<4;l++){
        int idx=tid+l*256;
        *(float4*)(b2 + (idx>>4)*68 + (idx&15)*4) =
            *(const float4*)(pkv + (size_t)h*4096 + (size_t)idx*4);
    }
    __syncthreads();
    float PP[4][4]={};
    for (int d=0;d<64;d++){
        float4 qq=*(float4*)(b1+d*68+i0);
        float4 aa=*(float4*)(b2+d*68+e0);
        float qr[4]={qq.x,qq.y,qq.z,qq.w}, ar[4]={aa.x,aa.y,aa.z,aa.w};
#pragma unroll
        for (int ii=0;ii<4;ii++)
#pragma unroll
        for (int ee=0;ee<4;ee++) PP[ii][ee]+=qr[ii]*ar[ee];
    }
    // PT -> b1, V -> b2 ; R = gamma^{i+1} QS + P @ V
    __syncthreads();
#pragma unroll
    for (int ii=0;ii<4;ii++)
#pragma unroll
    for (int ss=0;ss<4;ss++) b1[(s0+ss)*68 + (i0+ii)] = P[ii][ss];
#pragma unroll
    for (int l=0;l<4;l++){
        int idx=tid+l*256;
        *(float4*)(b2 + (idx>>4)*68 + (idx&15)*4) =
            *(const float4*)(g_v + base + (size_t)idx*4);
    }
    __syncthreads();
    float R[4][4];
#pragma unroll
    for (int ii=0;ii<4;ii++){
        float gi = gp[i0+ii+1];
#pragma unroll
        for (int ee=0;ee<4;ee++) R[ii][ee] = gi*QS[ii][ee];
    }
    for (int s=0;s<64;s++){
        float4 pt=*(float4*)(b1+s*68+i0);
        float4 vv=*(float4*)(b2+s*68+e0);
        float pr[4]={pt.x,pt.y,pt.z,pt.w}, vr[4]={vv.x,vv.y,vv.z,vv.w};
#pragma unroll
        for (int ii=0;ii<4;ii++)
#pragma unroll
        for (int ee=0;ee<4;ee++) R[ii][ee]+=pr[ii]*vr[ee];
    }
    // PP -> b1 as [i][e]; parallel suffix scan
    __syncthreads();
#pragma unroll
    for (int ii=0;ii<4;ii++)
#pragma unroll
    for (int ee=0;ee<4;ee++) b1[(i0+ii)*68 + (e0+ee)] = PP[ii][ee];
    __syncthreads();
#pragma unroll
    for (int st=1; st<64; st<<=1){
        float gs = gp[st];
        float tmp[16];
#pragma unroll
        for (int l=0;l<16;l++){
            int idx = tid + l*256;
            int i = idx>>6, e = idx&63;
            float v = b1[i*68+e];
            if (i+st<64) v += gs*b1[(i+st)*68+e];
            tmp[l]=v;
        }
        __syncthreads();
#pragma unroll
        for (int l=0;l<16;l++){
            int idx = tid + l*256;
            b1[(idx>>6)*68 + (idx&63)] = tmp[l];
        }
        __syncthreads();
    }
    // final add + stats
    float s1=0.f, s2=0.f;
#pragma unroll
    for (int ii=0;ii<4;ii++){
        float gx = gp[64-(i0+ii)];
#pragma unroll
        for (int ee=0;ee<4;ee++){
            float val = R[ii][ee] + b1[(i0+ii)*68 + (e0+ee)] + gx*Xs[e0+ee];
            R[ii][ee]=val;
            s1 += val; s2 += val*val;
        }
        *(float4*)(g_ret + base + (size_t)(i0+ii)*64 + e0) =
            make_float4(R[ii][0],R[ii][1],R[ii][2],R[ii][3]);
    }
#pragma unroll
    for (int o=16;o>0;o>>=1){
        s1 += __shfl_down_sync(0xffffffffu, s1, o);
        s2 += __shfl_down_sync(0xffffffffu, s2, o);
    }
    if ((tid&31)==0){ redS[tid>>5]=s1; redQ[tid>>5]=s2; }
    __syncthreads();
    if (tid==0){
        float a=0.f,bq=0.f;
#pragma unroll
        for (int w=0;w<8;w++){ a+=redS[w]; bq+=redQ[w]; }
        g_stat[(size_t)bid*2  ]=a;
        g_stat[(size_t)bid*2+1]=bq;
    }
}

// ================= K5: per-batch GroupNorm stats =================
__global__ void __launch_bounds__(512) k_stats()
{
    __shared__ float r1[512], r2[512];
    int b=blockIdx.x, tid=threadIdx.x;
    r1[tid]=g_stat[(size_t)(b*512+tid)*2];
    r2[tid]=g_stat[(size_t)(b*512+tid)*2+1];
    __syncthreads();
    for (int o=256;o>0;o>>=1){
        if (tid<o){ r1[tid]+=r1[tid+o]; r2[tid]+=r2[tid+o]; }
        __syncthreads();
    }
    if (tid==0){
        const float N = (float)((size_t)NH*NT*ND);
        float mu = r1[0]/N;
        float var = r2[0]/N - mu*mu;
        g_norm[b*2]=mu;
        g_norm[b*2+1]=rsqrtf(var+1e-5f);
    }
}

// ================= K6: normalize + layout to [B,T,NE] =================
__global__ void __launch_bounds__(256) k_out(const float* __restrict__ gnw,
                                             const float* __restrict__ gnb,
                                             float* __restrict__ out)
{
    int bid=blockIdx.x;
    int b=bid>>11, t=bid&2047;
    int tid=threadIdx.x;
    int h=tid>>4, d4=(tid&15)*4;
    float mu=g_norm[b*2], rs=g_norm[b*2+1];
    float w = gnw[h]*rs;
    float bb = gnb[h] - mu*w;
    float4 xv = *(const float4*)(g_ret + (((size_t)(b*NH+h))*NT + t)*ND + d4);
    float4 yv = make_float4(xv.x*w+bb, xv.y*w+bb, xv.z*w+bb, xv.w*w+bb);
    *(float4*)(out + (size_t)bid*NE + h*ND + d4) = yv;
}

// ================= K7: kv reduce + decay =================
__global__ void __launch_bounds__(256) k_kvout(const float* __restrict__ pkv,
                                               float* __restrict__ out_kv)
{
    int h=blockIdx.x;
    int idx=blockIdx.y*256+threadIdx.x;
    float s=0.f;
    for (int b=0;b<NB;b++){
        size_t bh=((size_t)(b*NH+h))*NCHK;
        for (int j2=0;j2<NCHK;j2++) s += g_kvc[(bh+j2)*4096 + idx];
    }
    double gd = 1.0 - exp2(-5.0-(double)h);
    out_kv[(size_t)h*4096 + idx] = (float)gd*pkv[(size_t)h*4096 + idx] + 0.25f*s;
}

extern "C" void kernel_launch(void* const* d_in, const int* in_sizes, int n_in,
                              void* d_out, int out_size)
{
    const float* x   = (const float*)d_in[0];
    const float* pkv = (const float*)d_in[1];
    const float* Wq  = (const float*)d_in[2];
    const float* Wk  = (const float*)d_in[3];
    const float* Wv  = (const float*)d_in[4];
    const float* gnw = (const float*)d_in[5];
    const float* gnb = (const float*)d_in[6];
    float* out = (float*)d_out;

    dim3 gproj(8, 64, 3);
    k_proj3<<<gproj, 256>>>(x, Wq, Wk, Wv);
    k_pass1<<<NBH*NCHK, 256>>>(pkv);
    k_scan<<<NBH, 256>>>();
    k_pass3<<<NBH*NCHK, 256>>>(pkv);
    k_stats<<<NB, 512>>>();
    k_out<<<NB*NT, 256>>>(gnw, gnb, out);
    dim3 gkv(NH, 16);
    k_kvout<<<gkv, 256>>>(pkv, out + (size_t)NB*NT*NE);
}

// round 4
// speedup vs baseline: 1.8397x; 1.2127x over previous
#include <cuda_runtime.h>
#include <math.h>
#include <stdint.h>

#define NB 4
#define NT 2048
#define NH 16
#define ND 64
#define NE 1024
#define NC 64
#define NCHK 32
#define NBH (NB*NH)

// ---------------- scratch (device globals; no runtime allocation) ----------------
__device__ float g_q  [(size_t)NB*NH*NT*ND];
__device__ float g_k  [(size_t)NB*NH*NT*ND];
__device__ float g_v  [(size_t)NB*NH*NT*ND];
__device__ float g_ret[(size_t)NB*NH*NT*ND];
__device__ float g_U  [(size_t)NBH*NCHK*ND*ND];
__device__ float g_S  [(size_t)NBH*NCHK*ND*ND];
__device__ float g_kvc[(size_t)NBH*NCHK*ND*ND];
__device__ float g_W  [(size_t)NBH*NCHK*ND];
__device__ float g_Xn [(size_t)NBH*NCHK*ND];
__device__ float g_stat[(size_t)NBH*NCHK*2];
__device__ float g_norm[NB*2];

__device__ __forceinline__ unsigned f2tf(float x){
    unsigned r;
    asm("cvt.rna.tf32.f32 %0, %1;" : "=r"(r) : "f"(x));
    return r;
}
__device__ __forceinline__ float tfr(float x){
    return __uint_as_float(f2tf(x));
}
__device__ __forceinline__ void mma8(float c[4], const unsigned a[4], unsigned b0, unsigned b1){
    asm volatile(
      "mma.sync.aligned.m16n8k8.row.col.f32.tf32.tf32.f32 "
      "{%0,%1,%2,%3},{%4,%5,%6,%7},{%8,%9},{%0,%1,%2,%3};"
      : "+f"(c[0]),"+f"(c[1]),"+f"(c[2]),"+f"(c[3])
      : "r"(a[0]),"r"(a[1]),"r"(a[2]),"r"(a[3]), "r"(b0),"r"(b1));
}

#define CP16(dst_u32, src) \
    asm volatile("cp.async.ca.shared.global [%0], [%1], 16;" :: "r"(dst_u32), "l"(src))

// ================= K1: fused QKV projection (TF32 mma, 3-stage cp.async) ===
#define PROJ_SMEM (3*(2560+2176)*4)
__global__ void __launch_bounds__(256) k_proj3(const float* __restrict__ X,
                                               const float* __restrict__ Wq,
                                               const float* __restrict__ Wk,
                                               const float* __restrict__ Wv)
{
    const int sel = blockIdx.z;
    const float* W = (sel==0)?Wq:(sel==1)?Wk:Wv;
    float* dst = (sel==0)?g_q:(sel==1)?g_k:g_v;

    extern __shared__ float dsm[];
    float* As = dsm;            // 3 stages of 128*20
    float* Bs = dsm + 3*2560;   // 3 stages of 16*136

    const int tid = threadIdx.x;
    const int rowBase = blockIdx.y*128, colBase = blockIdx.x*128;
    const int warp = tid>>5, lane = tid&31;
    const int wm = warp&3, wn = warp>>2;
    const int g = lane>>2, t4 = lane&3;

    const int ar0 = tid>>2, ac0 = (tid&3)*4;
    const int br0 = tid>>5, bc0 = (tid&31)*4;

    const unsigned sA = (unsigned)__cvta_generic_to_shared(As);
    const unsigned sB = (unsigned)__cvta_generic_to_shared(Bs);
    const unsigned stA = 2560u*4u, stB = 2176u*4u;

    float acc[2][8][4];
#pragma unroll
    for (int a=0;a<2;a++)
#pragma unroll
      for (int b=0;b<8;b++)
#pragma unroll
        for (int c=0;c<4;c++) acc[a][b][c]=0.f;

    auto issue = [&](int it, int st){
        int kb = it*16;
        const float* xs = X + (size_t)rowBase*NE + kb;
        CP16(sA + st*stA + (unsigned)((ar0    )*20 + ac0)*4u, xs + (size_t)(ar0    )*NE + ac0);
        CP16(sA + st*stA + (unsigned)((ar0+64 )*20 + ac0)*4u, xs + (size_t)(ar0+64 )*NE + ac0);
        const float* ws = W + (size_t)kb*NE + colBase;
        CP16(sB + st*stB + (unsigned)((br0   )*136 + bc0)*4u, ws + (size_t)(br0   )*NE + bc0);
        CP16(sB + st*stB + (unsigned)((br0+8 )*136 + bc0)*4u, ws + (size_t)(br0+8 )*NE + bc0);
        asm volatile("cp.async.commit_group;" ::: "memory");
    };

    const int NIT = NE/16;
    issue(0,0); issue(1,1);
    for (int it=0; it<NIT; it++){
        const int st = it%3;
        if (it+2<NIT){
            issue(it+2, (it+2)%3);
            asm volatile("cp.async.wait_group 2;" ::: "memory");
        } else if (it+1<NIT){
            asm volatile("cp.async.wait_group 1;" ::: "memory");
        } else {
            asm volatile("cp.async.wait_group 0;" ::: "memory");
        }
        __syncthreads();
        const float* Ap = As + st*2560;
        const float* Bp = Bs + st*2176;
#pragma unroll
        for (int k0=0;k0<16;k0+=8){
            unsigned af[2][4];
#pragma unroll
            for (int mt=0;mt<2;mt++){
                int r0 = wm*32 + mt*16;
                af[mt][0] = f2tf(Ap[(r0+g  )*20 + k0 + t4    ]);
                af[mt][1] = f2tf(Ap[(r0+g+8)*20 + k0 + t4    ]);
                af[mt][2] = f2tf(Ap[(r0+g  )*20 + k0 + t4 + 4]);
                af[mt][3] = f2tf(Ap[(r0+g+8)*20 + k0 + t4 + 4]);
            }
#pragma unroll
            for (int nt=0;nt<8;nt++){
                int c0 = wn*64 + nt*8;
                unsigned b0 = f2tf(Bp[(k0+t4  )*136 + c0 + g]);
                unsigned b1 = f2tf(Bp[(k0+t4+4)*136 + c0 + g]);
#pragma unroll
                for (int mt=0;mt<2;mt++){
                    mma8(acc[mt][nt], af[mt], b0, b1);
                }
            }
        }
        __syncthreads();
    }
#pragma unroll
    for (int mt=0;mt<2;mt++)
#pragma unroll
    for (int nt=0;nt<8;nt++){
        int row = rowBase + wm*32 + mt*16 + g;
        int col = colBase + wn*64 + nt*8 + t4*2;
        int b_ = row>>11, t_ = row&2047, h_ = col>>6, d_ = col&63;
        float* p0 = dst + (((size_t)(b_*NH+h_))*NT + t_)*ND + d_;
        *(float2*)p0 = make_float2(acc[mt][nt][0], acc[mt][nt][1]);
        int row2 = row+8;
        int t2_ = row2&2047;
        float* p1 = dst + (((size_t)(b_*NH+h_))*NT + t2_)*ND + d_;
        *(float2*)p1 = make_float2(acc[mt][nt][2], acc[mt][nt][3]);
    }
}

// ================= K2: per-chunk U_j, KV_j (tensor core), W_j =================
__global__ void __launch_bounds__(256) k_pass1(const float* __restrict__ pkv)
{
    __shared__ float bufA[64*68];   // KT [d][i] (tf32)
    __shared__ float bufB[64*72];   // V [i][e] (tf32) -> Vw -> Q raw
    __shared__ float gp[65];
    __shared__ float red[4*64];
    __shared__ float qw[64];
    int tid=threadIdx.x, bid=blockIdx.x;
    int j=bid&31, bh=bid>>5, h=bh&15;
    size_t base = ((size_t)bh*NT + (size_t)j*NC)*ND;
    if (tid<=64){
        double gd = 1.0 - exp2(-5.0-(double)h);
        gp[tid]=(float)pow(gd,(double)tid);
    }
#pragma unroll
    for (int l=0;l<4;l++){
        int idx = tid + l*256;
        int i=idx>>4, d4=(idx&15)*4;
        float4 k4 = *(const float4*)(g_k + base + (size_t)idx*4);
        bufA[(d4  )*68+i]=tfr(k4.x);
        bufA[(d4+1)*68+i]=tfr(k4.y);
        bufA[(d4+2)*68+i]=tfr(k4.z);
        bufA[(d4+3)*68+i]=tfr(k4.w);
        float4 v4 = *(const float4*)(g_v + base + (size_t)idx*4);
        bufB[i*72+d4  ]=tfr(v4.x);
        bufB[i*72+d4+1]=tfr(v4.y);
        bufB[i*72+d4+2]=tfr(v4.z);
        bufB[i*72+d4+3]=tfr(v4.w);
    }
    __syncthreads();
    const int warp=tid>>5, lane=tid&31;
    const int wm=warp&3, wn=warp>>2, g=lane>>2, t4=lane&3;
    const int m0=wm*16;
    const int r0=m0+g, r1=r0+8;

    auto mmaloop = [&](float acc[4][4]){
#pragma unroll
        for (int k=0;k<64;k+=8){
            unsigned aa[4];
            aa[0]=__float_as_uint(bufA[(m0+g  )*68 + k+t4  ]);
            aa[1]=__float_as_uint(bufA[(m0+g+8)*68 + k+t4  ]);
            aa[2]=__float_as_uint(bufA[(m0+g  )*68 + k+t4+4]);
            aa[3]=__float_as_uint(bufA[(m0+g+8)*68 + k+t4+4]);
#pragma unroll
            for (int nt=0;nt<4;nt++){
                int cb=wn*32+nt*8;
                unsigned b0=__float_as_uint(bufB[(k+t4  )*72 + cb+g]);
                unsigned b1=__float_as_uint(bufB[(k+t4+4)*72 + cb+g]);
                mma8(acc[nt], aa, b0, b1);
            }
        }
    };

    // KV = K^T V  (unweighted)
    {
        float accKV[4][4]={};
        mmaloop(accKV);
        float* Kp = g_kvc + (size_t)bid*4096;
#pragma unroll
        for (int nt=0;nt<4;nt++){
            int c0=wn*32+nt*8+t4*2;
            *(float2*)(Kp + r0*64 + c0) = make_float2(accKV[nt][0],accKV[nt][1]);
            *(float2*)(Kp + r1*64 + c0) = make_float2(accKV[nt][2],accKV[nt][3]);
        }
    }
    __syncthreads();
    // rescale V in place: Vw[i][e] = gamma^{63-i} V[i][e]
#pragma unroll
    for (int l=0;l<4;l++){
        int idx=tid+l*256;
        int i=idx>>4, c4=(idx&15)*4;
        float w = gp[63-i];
        float4 v = *(float4*)(bufB + i*72 + c4);
        v.x=tfr(v.x*w); v.y=tfr(v.y*w); v.z=tfr(v.z*w); v.w=tfr(v.w*w);
        *(float4*)(bufB + i*72 + c4) = v;
    }
    __syncthreads();
    // U = K^T Vw
    {
        float accU[4][4]={};
        mmaloop(accU);
        float* Up = g_U + (size_t)bid*4096;
#pragma unroll
        for (int nt=0;nt<4;nt++){
            int c0=wn*32+nt*8+t4*2;
            *(float2*)(Up + r0*64 + c0) = make_float2(accU[nt][0],accU[nt][1]);
            *(float2*)(Up + r1*64 + c0) = make_float2(accU[nt][2],accU[nt][3]);
        }
    }
    __syncthreads();
    // Q raw into bufB
#pragma unroll
    for (int l=0;l<4;l++){
        int idx=tid+l*256;
        *(float4*)(bufB + (idx>>4)*72 + (idx&15)*4) =
            *(const float4*)(g_q + base + (size_t)idx*4);
    }
    __syncthreads();
    // qw[d] = sum_i gamma^i q[i,d]
    int rr = tid>>6, d = tid&63;
    float s = 0.f;
#pragma unroll
    for (int i=rr*16;i<rr*16+16;i++) s += gp[i]*bufB[i*72 + d];
    red[rr*64 + d] = s;
    __syncthreads();
    if (tid<64) qw[tid] = red[tid] + red[64+tid] + red[128+tid] + red[192+tid];
    __syncthreads();
    // W_j[e] = sum_d qw[d] * A[d,e]
    const float* A = pkv + (size_t)h*4096;
    float s2 = 0.f;
#pragma unroll
    for (int dd=rr*16; dd<rr*16+16; dd++) s2 += qw[dd]*A[dd*64 + d];
    red[rr*64 + d] = s2;
    __syncthreads();
    if (tid<64) g_W[(size_t)bid*64 + tid] = red[tid] + red[64+tid] + red[128+tid] + red[192+tid];
}

// ================= K3: chunk scans (forward state, backward suffix carry) =========
__global__ void __launch_bounds__(256) k_scan()
{
    int bh = blockIdx.x, part = blockIdx.y, tid = threadIdx.x;
    int h = bh&15;
    double gd = 1.0 - exp2(-5.0-(double)h);
    float g64 = (float)pow(gd,64.0);
    float S[4] = {0.f,0.f,0.f,0.f};
    int off = part*1024;
    for (int j=0;j<NCHK;j++){
        size_t o = ((size_t)bh*NCHK+j)*4096 + off;
#pragma unroll
        for (int r=0;r<4;r++){
            int idx = tid + r*256;
            g_S[o+idx] = S[r];
            S[r] = g64*S[r] + g_U[o+idx];
        }
    }
    if (part==0 && tid<64){
        float X=0.f;
        for (int j=NCHK-1;j>=0;--j){
            size_t o2 = ((size_t)bh*NCHK+j)*64;
            g_Xn[o2+tid] = X;
            X = g64*X + g_W[o2+tid];
        }
    }
}

// ================= K4: per-chunk finalize (tensor core) =================
__global__ void __launch_bounds__(256) k_pass3(const float* __restrict__ pkv)
{
    __shared__ float bufA[64*68];   // Q (tf32) -> P (tf32) -> PP (fp32)
    __shared__ float bufB[64*72];   // KT -> S -> pkv -> V (tf32)
    __shared__ float gp[65];
    __shared__ float Xs[64];
    __shared__ float redS[8], redQ[8];
    int tid=threadIdx.x, bid=blockIdx.x;
    int j=bid&31, bh=bid>>5, h=bh&15;
    size_t base=((size_t)bh*NT+(size_t)j*NC)*ND;
    if (tid<=64){
        double gd = 1.0 - exp2(-5.0-(double)h);
        gp[tid]=(float)pow(gd,(double)tid);
    }
    if (tid<64) Xs[tid] = g_Xn[((size_t)bh*NCHK+j)*64 + tid];

    // Q natural -> bufA (tf32), KT transposed -> bufB (tf32)
#pragma unroll
    for (int l=0;l<4;l++){
        int idx=tid+l*256;
        int i=idx>>4, d4=(idx&15)*4;
        float4 q4 = *(const float4*)(g_q + base + (size_t)idx*4);
        bufA[i*68+d4  ]=tfr(q4.x);
        bufA[i*68+d4+1]=tfr(q4.y);
        bufA[i*68+d4+2]=tfr(q4.z);
        bufA[i*68+d4+3]=tfr(q4.w);
        float4 k4 = *(const float4*)(g_k + base + (size_t)idx*4);
        bufB[(d4  )*72+i]=tfr(k4.x);
        bufB[(d4+1)*72+i]=tfr(k4.y);
        bufB[(d4+2)*72+i]=tfr(k4.z);
        bufB[(d4+3)*72+i]=tfr(k4.w);
    }
    __syncthreads();
    const int warp=tid>>5, lane=tid&31;
    const int wm=warp&3, wn=warp>>2, g=lane>>2, t4=lane&3;
    const int m0=wm*16;
    const int r0=m0+g, r1=r0+8;

    auto mmaloop = [&](float acc[4][4]){
#pragma unroll
        for (int k=0;k<64;k+=8){
            unsigned aa[4];
            aa[0]=__float_as_uint(bufA[(m0+g  )*68 + k+t4  ]);
            aa[1]=__float_as_uint(bufA[(m0+g+8)*68 + k+t4  ]);
            aa[2]=__float_as_uint(bufA[(m0+g  )*68 + k+t4+4]);
            aa[3]=__float_as_uint(bufA[(m0+g+8)*68 + k+t4+4]);
#pragma unroll
            for (int nt=0;nt<4;nt++){
                int cb=wn*32+nt*8;
                unsigned b0=__float_as_uint(bufB[(k+t4  )*72 + cb+g]);
                unsigned b1=__float_as_uint(bufB[(k+t4+4)*72 + cb+g]);
                mma8(acc[nt], aa, b0, b1);
            }
        }
    };
    auto loadB = [&](const float* src){
#pragma unroll
        for (int l=0;l<4;l++){
            int idx=tid+l*256;
            float4 v4 = *(const float4*)(src + (size_t)idx*4);
            int r=idx>>4, c=(idx&15)*4;
            bufB[r*72+c  ]=tfr(v4.x);
            bufB[r*72+c+1]=tfr(v4.y);
            bufB[r*72+c+2]=tfr(v4.z);
            bufB[r*72+c+3]=tfr(v4.w);
        }
    };

    float accP[4][4]={}, accQ[4][4]={}, accPP[4][4]={};
    // P = Q K^T
    mmaloop(accP);
    __syncthreads();
    loadB(g_S + ((size_t)bh*NCHK+j)*4096);
    __syncthreads();
    // QS = Q S
    mmaloop(accQ);
    __syncthreads();
    loadB(pkv + (size_t)h*4096);
    __syncthreads();
    // PP = Q A
    mmaloop(accPP);
    __syncthreads();   // all reads of bufA (Q) done
    // decay P -> bufA (tf32); scale accQ by gamma^{row+1}
#pragma unroll
    for (int nt=0;nt<4;nt++){
        int c0=wn*32+nt*8+t4*2;
        int d00=r0-c0, d01=d00-1, d10=r1-c0, d11=d10-1;
        float p00 = (d00>=0)? accP[nt][0]*gp[d00] : 0.f;
        float p01 = (d01>=0)? accP[nt][1]*gp[d01] : 0.f;
        float p10 = (d10>=0)? accP[nt][2]*gp[d10] : 0.f;
        float p11 = (d11>=0)? accP[nt][3]*gp[d11] : 0.f;
        bufA[r0*68+c0  ]=tfr(p00);
        bufA[r0*68+c0+1]=tfr(p01);
        bufA[r1*68+c0  ]=tfr(p10);
        bufA[r1*68+c0+1]=tfr(p11);
        float gq0=gp[r0+1], gq1=gp[r1+1];
        accQ[nt][0]*=gq0; accQ[nt][1]*=gq0;
        accQ[nt][2]*=gq1; accQ[nt][3]*=gq1;
    }
    __syncthreads();
    loadB(g_v + base);
    __syncthreads();
    // R = gamma^{i+1} QS + P V
    mmaloop(accQ);
    __syncthreads();   // reads of bufA (P) done
    // PP -> bufA (fp32)
#pragma unroll
    for (int nt=0;nt<4;nt++){
        int c0=wn*32+nt*8+t4*2;
        *(float2*)(bufA + r0*68 + c0) = make_float2(accPP[nt][0],accPP[nt][1]);
        *(float2*)(bufA + r1*68 + c0) = make_float2(accPP[nt][2],accPP[nt][3]);
    }
    __syncthreads();
    // parallel suffix scan over rows of bufA [i][e]
#pragma unroll
    for (int st=1; st<64; st<<=1){
        float gs = gp[st];
        float tmp[16];
#pragma unroll
        for (int l=0;l<16;l++){
            int idx = tid + l*256;
            int i = idx>>6, e = idx&63;
            float v = bufA[i*68+e];
            if (i+st<64) v += gs*bufA[(i+st)*68+e];
            tmp[l]=v;
        }
        __syncthreads();
#pragma unroll
        for (int l=0;l<16;l++){
            int idx = tid + l*256;
            bufA[(idx>>6)*68 + (idx&63)] = tmp[l];
        }
        __syncthreads();
    }
    // final add + stats + store
    float s1=0.f, s2=0.f;
    float gx0=gp[64-r0], gx1=gp[64-r1];
#pragma unroll
    for (int nt=0;nt<4;nt++){
        int c0=wn*32+nt*8+t4*2;
        float v00 = accQ[nt][0] + bufA[r0*68+c0  ] + gx0*Xs[c0  ];
        float v01 = accQ[nt][1] + bufA[r0*68+c0+1] + gx0*Xs[c0+1];
        float v10 = accQ[nt][2] + bufA[r1*68+c0  ] + gx1*Xs[c0  ];
        float v11 = accQ[nt][3] + bufA[r1*68+c0+1] + gx1*Xs[c0+1];
        s1 += v00+v01+v10+v11;
        s2 += v00*v00+v01*v01+v10*v10+v11*v11;
        *(float2*)(g_ret + base + (size_t)r0*64 + c0) = make_float2(v00,v01);
        *(float2*)(g_ret + base + (size_t)r1*64 + c0) = make_float2(v10,v11);
    }
#pragma unroll
    for (int o=16;o>0;o>>=1){
        s1 += __shfl_down_sync(0xffffffffu, s1, o);
        s2 += __shfl_down_sync(0xffffffffu, s2, o);
    }
    if (lane==0){ redS[warp]=s1; redQ[warp]=s2; }
    __syncthreads();
    if (tid==0){
        float a=0.f,bq=0.f;
#pragma unroll
        for (int w=0;w<8;w++){ a+=redS[w]; bq+=redQ[w]; }
        g_stat[(size_t)bid*2  ]=a;
        g_stat[(size_t)bid*2+1]=bq;
    }
}

// ================= K5: per-batch GroupNorm stats =================
__global__ void __launch_bounds__(512) k_stats()
{
    __shared__ float r1[512], r2[512];
    int b=blockIdx.x, tid=threadIdx.x;
    r1[tid]=g_stat[(size_t)(b*512+tid)*2];
    r2[tid]=g_stat[(size_t)(b*512+tid)*2+1];
    __syncthreads();
    for (int o=256;o>0;o>>=1){
        if (tid<o){ r1[tid]+=r1[tid+o]; r2[tid]+=r2[tid+o]; }
        __syncthreads();
    }
    if (tid==0){
        const float N = (float)((size_t)NH*NT*ND);
        float mu = r1[0]/N;
        float var = r2[0]/N - mu*mu;
        g_norm[b*2]=mu;
        g_norm[b*2+1]=rsqrtf(var+1e-5f);
    }
}

// ================= K6: normalize + layout to [B,T,NE] =================
__global__ void __launch_bounds__(256) k_out(const float* __restrict__ gnw,
                                             const float* __restrict__ gnb,
                                             float* __restrict__ out)
{
    int bid=blockIdx.x;
    int b=bid>>11, t=bid&2047;
    int tid=threadIdx.x;
    int h=tid>>4, d4=(tid&15)*4;
    float mu=g_norm[b*2], rs=g_norm[b*2+1];
    float w = gnw[h]*rs;
    float bb = gnb[h] - mu*w;
    float4 xv = *(const float4*)(g_ret + (((size_t)(b*NH+h))*NT + t)*ND + d4);
    float4 yv = make_float4(xv.x*w+bb, xv.y*w+bb, xv.z*w+bb, xv.w*w+bb);
    *(float4*)(out + (size_t)bid*NE + h*ND + d4) = yv;
}

// ================= K7: kv reduce + decay =================
__global__ void __launch_bounds__(256) k_kvout(const float* __restrict__ pkv,
                                               float* __restrict__ out_kv)
{
    int h=blockIdx.x;
    int idx=blockIdx.y*256+threadIdx.x;
    float s=0.f;
    for (int b=0;b<NB;b++){
        size_t bh=((size_t)(b*NH+h))*NCHK;
        for (int j2=0;j2<NCHK;j2++) s += g_kvc[(bh+j2)*4096 + idx];
    }
    double gd = 1.0 - exp2(-5.0-(double)h);
    out_kv[(size_t)h*4096 + idx] = (float)gd*pkv[(size_t)h*4096 + idx] + 0.25f*s;
}

extern "C" void kernel_launch(void* const* d_in, const int* in_sizes, int n_in,
                              void* d_out, int out_size)
{
    const float* x   = (const float*)d_in[0];
    const float* pkv = (const float*)d_in[1];
    const float* Wq  = (const float*)d_in[2];
    const float* Wk  = (const float*)d_in[3];
    const float* Wv  = (const float*)d_in[4];
    const float* gnw = (const float*)d_in[5];
    const float* gnb = (const float*)d_in[6];
    float* out = (float*)d_out;

    cudaFuncSetAttribute(k_proj3, cudaFuncAttributeMaxDynamicSharedMemorySize, PROJ_SMEM);

    dim3 gproj(8, 64, 3);
    k_proj3<<<gproj, 256, PROJ_SMEM>>>(x, Wq, Wk, Wv);
    k_pass1<<<NBH*NCHK, 256>>>(pkv);
    dim3 gscan(NBH, 4);
    k_scan<<<gscan, 256>>>();
    k_pass3<<<NBH*NCHK, 256>>>(pkv);
    k_stats<<<NB, 512>>>();
    k_out<<<NB*NT, 256>>>(gnw, gnb, out);
    dim3 gkv(NH, 16);
    k_kvout<<<gkv, 256>>>(pkv, out + (size_t)NB*NT*NE);
}